// round 10
// baseline (speedup 1.0000x reference)
#include <cuda_runtime.h>
#include <cuda_bf16.h>
#include <math.h>
#include <stdint.h>

// Problem constants (fixed by the dataset)
#define B_   16384
#define E_   128
#define S_   512
#define VOC_ 1000000

#define NGEMM 512                     // 128 row-tiles x 4 col-tiles
#define NTRUE 256                     // 64 true rows each
#define NTOT  (NGEMM + NTRUE)

#define TILE_BYTES 32768              // 128 rows x 128 bf16 (256B/row)
#define DYN_SMEM (2 * TILE_BYTES)

// ---- device scratch (no allocations allowed) ----
__device__ float g_part[NTOT];
__device__ unsigned int g_done;       // zero-init; reset by last block each run

__device__ __forceinline__ uint32_t smem_u32(const void* p) {
    uint32_t a;
    asm("{ .reg .u64 t; cvta.to.shared.u64 t, %1; cvt.u32.u64 %0, t; }"
        : "=r"(a) : "l"(p));
    return a;
}

// Swizzled tile layout: [row r][16B chunk c], phys chunk = c ^ (r&7).
__device__ __forceinline__ uint32_t tile_off(int r, int c) {
    return (uint32_t)(r * 256 + ((c ^ (r & 7)) << 4));
}

__device__ __forceinline__ int load_id(const void* p, int i, int idx64) {
    long long v;
    if (idx64) v = ((const long long*)p)[i];
    else       v = (long long)((const int*)p)[i];
    if (v < 0) v = 0;
    if (v >= VOC_) v = VOC_ - 1;
    return (int)v;
}

// -------------------------------------------------------------------------
// Reference-faithful  -log(expected_count(id))  (cancellation-safe: f32
// log(c+2)-log(c+1) cancels catastrophically; use CR f32 logs via double)
// -------------------------------------------------------------------------
__device__ __forceinline__ float neg_log_expected(int id) {
    double cd = (double)id;
    float l2 = (float)log(cd + 2.0);
    float l1 = (float)log(cd + 1.0);
    float denom = (float)log((double)VOC_ + 1.0);
    float p = (l2 - l1) / denom;
    float lp = log1pf(-p);
    float e  = -expm1f(512.0f * lp);
    return -logf(e);
}

// -------------------------------------------------------------------------
// Fast softplus: max(x,0) + log1p(exp(-|x|)); FMA/ALU hot path.
// -------------------------------------------------------------------------
__device__ __forceinline__ float softplus_fast(float x) {
    float u  = fabsf(x);
    float mx = fmaxf(x, 0.0f);
    float y  = fmaxf(u * -1.4426950408889634f, -25.0f);
    int   n  = __float2int_rn(y);
    float f  = y - (float)n;
    float pe = 1.3333558146e-3f;
    pe = fmaf(pe, f, 9.6181291076e-3f);
    pe = fmaf(pe, f, 5.5504108665e-2f);
    pe = fmaf(pe, f, 2.4022650696e-1f);
    pe = fmaf(pe, f, 6.9314718056e-1f);
    pe = fmaf(pe, f, 1.0f);
    float t = pe * __int_as_float((n + 127) << 23);
    float l;
    if (t > 0.125f) {
        l = log1pf(t);
    } else {
        l = t * fmaf(t, fmaf(t, fmaf(t, -0.25f, 0.33333333f), -0.5f), 1.0f);
    }
    return mx + l;
}

__device__ __forceinline__ uint32_t pack_bf(float a, float b) {
    __nv_bfloat162 h = __floats2bfloat162_rn(a, b);
    return *reinterpret_cast<uint32_t*>(&h);
}

#define LDMX4(r0, r1, r2, r3, addr) \
    asm volatile("ldmatrix.sync.aligned.m8n8.x4.shared.b16 {%0,%1,%2,%3}, [%4];" \
                 : "=r"(r0), "=r"(r1), "=r"(r2), "=r"(r3) : "r"(addr))

#define MMA16816(c, a, b0, b1) \
    asm volatile("mma.sync.aligned.m16n8k16.row.col.f32.bf16.bf16.f32 " \
                 "{%0,%1,%2,%3}, {%4,%5,%6,%7}, {%8,%9}, {%0,%1,%2,%3};" \
                 : "+f"((c)[0]), "+f"((c)[1]), "+f"((c)[2]), "+f"((c)[3]) \
                 : "r"((a)[0]), "r"((a)[1]), "r"((a)[2]), "r"((a)[3]), \
                   "r"(b0), "r"(b1))

// -------------------------------------------------------------------------
// Single fused kernel.
//   blocks [0, 512):  128x128 GEMM tile (gather B from W in-block, corr
//                     computed in-block) + softplus + partial sum
//   blocks [512,768): 64 true rows each (corr in-lane, overlapped)
//   last block:       deterministic double-precision final reduction
// block = 256 threads (8 warps, 4x2), dyn smem = 64KB
// -------------------------------------------------------------------------
__global__ __launch_bounds__(256, 2)
void k_all(const float* __restrict__ P, const float* __restrict__ W,
           const float* __restrict__ bias, const void* __restrict__ labels,
           const void* __restrict__ sampled, float* __restrict__ out) {
    __shared__ float red[8];
    __shared__ float s_corr[128];
    __shared__ double dred[256];
    __shared__ unsigned int ticket;
    extern __shared__ char dyn[];

    const int bx = blockIdx.x;
    const int tid = threadIdx.x, lane = tid & 31, wid = tid >> 5;

    // Index dtype detection: 256 threads read the first 2048B of `sampled`
    // (valid for both int32[512] and int64[512]). If it's int32 data read as
    // int64, high words hold the next random id => OOB => int32.
    long long dv = ((const long long*)sampled)[tid];
    int idx64 = !__syncthreads_or(dv < 0 || dv >= (long long)VOC_);

    float partial = 0.0f;

    if (bx < NGEMM) {
        const int rowTile = bx >> 2, colTile = bx & 3;
        char* Abuf = dyn;
        char* Bbuf = dyn + TILE_BYTES;

        // Per-column correction (threads 0..127) — fp64 latency hides
        // behind the staging + mainloop below.
        if (tid < 128) {
            int id = load_id(sampled, colTile * 128 + tid, idx64);
            s_corr[tid] = bias[id] + neg_log_expected(id);
        }

        // Stage B: gather sampled weight rows, f32 -> bf16, swizzled.
#pragma unroll
        for (int i = 0; i < 8; i++) {
            int idx = tid + 256 * i;             // 0..2047
            int n = idx >> 4, c = idx & 15;
            int id = load_id(sampled, colTile * 128 + n, idx64);
            const float* src = W + (size_t)id * E_ + c * 8;
            float4 v0 = *(const float4*)src;
            float4 v1 = *(const float4*)(src + 4);
            uint4 u;
            u.x = pack_bf(v0.x, v0.y); u.y = pack_bf(v0.z, v0.w);
            u.z = pack_bf(v1.x, v1.y); u.w = pack_bf(v1.z, v1.w);
            *(uint4*)(Bbuf + tile_off(n, c)) = u;
        }
        // Stage A: predictions tile, f32 -> bf16, swizzled.
        const float* Abase = P + (size_t)rowTile * 128 * E_;
#pragma unroll
        for (int i = 0; i < 8; i++) {
            int idx = tid + 256 * i;
            int r = idx >> 4, c = idx & 15;
            const float* src = Abase + (size_t)r * E_ + c * 8;
            float4 v0 = *(const float4*)src;
            float4 v1 = *(const float4*)(src + 4);
            uint4 u;
            u.x = pack_bf(v0.x, v0.y); u.y = pack_bf(v0.z, v0.w);
            u.z = pack_bf(v1.x, v1.y); u.w = pack_bf(v1.z, v1.w);
            *(uint4*)(Abuf + tile_off(r, c)) = u;
        }
        __syncthreads();

        const int warpRow = wid & 3;          // m offset *32
        const int warpCol = wid >> 2;         // n offset *64
        const int lrow = lane & 15;
        const int lhi  = lane >> 4;

        const uint32_t a_s = smem_u32(Abuf);
        const uint32_t b_s = smem_u32(Bbuf);

        int arow[2], brow[4];
#pragma unroll
        for (int mi = 0; mi < 2; mi++) arow[mi] = warpRow * 32 + mi * 16 + lrow;
#pragma unroll
        for (int nj = 0; nj < 4; nj++) brow[nj] = warpCol * 64 + nj * 16 + lrow;

        float acc[2][8][4];
#pragma unroll
        for (int mi = 0; mi < 2; mi++)
#pragma unroll
            for (int ni = 0; ni < 8; ni++)
#pragma unroll
                for (int r = 0; r < 4; r++) acc[mi][ni][r] = 0.0f;

#pragma unroll
        for (int ks = 0; ks < 8; ks++) {
            const int chunk = ks * 2 + lhi;
            uint32_t a[2][4];
#pragma unroll
            for (int mi = 0; mi < 2; mi++) {
                uint32_t addr = a_s + (uint32_t)(arow[mi] * 256
                               + ((chunk ^ (arow[mi] & 7)) << 4));
                LDMX4(a[mi][0], a[mi][1], a[mi][2], a[mi][3], addr);
            }
            uint32_t bb[4][4];
#pragma unroll
            for (int nj = 0; nj < 4; nj++) {
                uint32_t addr = b_s + (uint32_t)(brow[nj] * 256
                               + ((chunk ^ (brow[nj] & 7)) << 4));
                LDMX4(bb[nj][0], bb[nj][1], bb[nj][2], bb[nj][3], addr);
            }
#pragma unroll
            for (int mi = 0; mi < 2; mi++)
#pragma unroll
                for (int ni = 0; ni < 8; ni++)
                    MMA16816(acc[mi][ni], a[mi],
                             bb[ni >> 1][ni & 1], bb[ni >> 1][2 + (ni & 1)]);
        }

        // Epilogue: cols warpCol*64 + ni*8 + q*2 (+1), q = lane&3
        const int q = lane & 3;
        const float* corrB = s_corr + warpCol * 64;
        float lsum = 0.0f;
#pragma unroll
        for (int ni = 0; ni < 8; ni++) {
            float c0 = corrB[ni * 8 + q * 2];
            float c1 = corrB[ni * 8 + q * 2 + 1];
#pragma unroll
            for (int mi = 0; mi < 2; mi++) {
                lsum += softplus_fast(acc[mi][ni][0] + c0);
                lsum += softplus_fast(acc[mi][ni][1] + c1);
                lsum += softplus_fast(acc[mi][ni][2] + c0);
                lsum += softplus_fast(acc[mi][ni][3] + c1);
            }
        }
        partial = lsum;
    } else {
        // True-class loss: 64 rows per block, 8 rows per warp.
        const int rowbase = (bx - NGEMM) * 64 + wid * 8;

        // Lanes 0..7 each compute the correction for one of the warp's rows
        // (fp64 latency overlaps the gathers below).
        int cid = 0;
        float mycorr = 0.0f;
        if (lane < 8) {
            cid = load_id(labels, rowbase + lane, idx64);
            mycorr = bias[cid] + neg_log_expected(cid);
        }

        float wsum = 0.0f;
        int id0 = __shfl_sync(0xFFFFFFFFu, cid, 0);
        float4 p4 = *(const float4*)(P + (size_t)rowbase * E_ + lane * 4);
        float4 w4 = *(const float4*)(W + (size_t)id0 * E_ + lane * 4);
#pragma unroll
        for (int i = 0; i < 8; i++) {
            float4 np, nw;
            if (i < 7) {
                int idn = __shfl_sync(0xFFFFFFFFu, cid, i + 1);
                np = *(const float4*)(P + (size_t)(rowbase + i + 1) * E_ + lane * 4);
                nw = *(const float4*)(W + (size_t)idn * E_ + lane * 4);
            } else {
                np = make_float4(0.f, 0.f, 0.f, 0.f);
                nw = np;
            }
            float d = p4.x * w4.x + p4.y * w4.y + p4.z * w4.z + p4.w * w4.w;
#pragma unroll
            for (int off = 16; off > 0; off >>= 1)
                d += __shfl_xor_sync(0xFFFFFFFFu, d, off);
            float ci = __shfl_sync(0xFFFFFFFFu, mycorr, i);
            if (lane == 0) {
                float x = d + ci;
                wsum += softplus_fast(x) - x;   // sce(x, z=1)
            }
            p4 = np; w4 = nw;
        }
        partial = (lane == 0) ? wsum : 0.0f;
    }

    // Block reduction: warp shuffle + one cross-warp stage.
#pragma unroll
    for (int off = 16; off > 0; off >>= 1)
        partial += __shfl_xor_sync(0xFFFFFFFFu, partial, off);
    if (lane == 0) red[wid] = partial;
    __syncthreads();
    if (tid == 0) {
        float t = 0.0f;
#pragma unroll
        for (int i = 0; i < 8; i++) t += red[i];
        g_part[bx] = t;
    }

    // Last-block deterministic final reduction.
    __threadfence();
    if (tid == 0) ticket = atomicAdd(&g_done, 1u);
    __syncthreads();
    if (ticket == NTOT - 1) {
        __threadfence();
        double s = 0.0;
        for (int i = tid; i < NTOT; i += 256) s += (double)g_part[i];
        dred[tid] = s;
        __syncthreads();
#pragma unroll
        for (int k = 128; k > 0; k >>= 1) {
            if (tid < k) dred[tid] += dred[tid + k];
            __syncthreads();
        }
        if (tid == 0) {
            out[0] = (float)(dred[0] / (double)B_);
            g_done = 0;                  // reset for next graph replay
        }
    }
}

// -------------------------------------------------------------------------
extern "C" void kernel_launch(void* const* d_in, const int* in_sizes, int n_in,
                              void* d_out, int out_size) {
    const float* pred    = (const float*)d_in[0];   // [B, E]
    const float* weights = (const float*)d_in[1];   // [V, E]
    const float* biases  = (const float*)d_in[2];   // [V]
    const void*  labels  = d_in[3];                 // [B, 1] int32 or int64
    const void*  sampled = d_in[4];                 // [S]
    float* out = (float*)d_out;

    static int attr_done = 0;
    if (!attr_done) {
        cudaFuncSetAttribute(k_all, cudaFuncAttributeMaxDynamicSharedMemorySize,
                             DYN_SMEM);
        attr_done = 1;
    }

    k_all<<<NTOT, 256, DYN_SMEM>>>(pred, weights, biases, labels, sampled, out);
}

// round 11
// speedup vs baseline: 1.7977x; 1.7977x over previous
#include <cuda_runtime.h>
#include <cuda_bf16.h>
#include <math.h>
#include <stdint.h>

// Problem constants (fixed by the dataset)
#define B_   16384
#define E_   128
#define S_   512
#define VOC_ 1000000

#define NGEMM 512                     // 128 row-tiles x 4 col-tiles
#define NTRUE 256                     // 64 true rows each
#define NTOT  (NGEMM + NTRUE)

#define TILE_BYTES 32768              // 128 rows x 128 bf16 (256B/row)
#define DYN_SMEM (2 * TILE_BYTES)

// ---- device scratch (no allocations allowed) ----
__device__ uint32_t g_Bsw[4 * TILE_BYTES / 4];   // pre-swizzled bf16 B tiles
__device__ float g_corr[S_];
__device__ float g_tcorr[B_];
__device__ float g_part[NTOT];
__device__ int   g_idx64;
__device__ unsigned int g_done;       // zero-init; last block resets each run

__device__ __forceinline__ uint32_t smem_u32(const void* p) {
    uint32_t a;
    asm("{ .reg .u64 t; cvta.to.shared.u64 t, %1; cvt.u32.u64 %0, t; }"
        : "=r"(a) : "l"(p));
    return a;
}

// Swizzled tile layout: [row r][16B chunk c], phys chunk = c ^ (r&7).
__device__ __forceinline__ uint32_t tile_off(int r, int c) {
    return (uint32_t)(r * 256 + ((c ^ (r & 7)) << 4));
}

// -------------------------------------------------------------------------
// Index dtype detection (per-block, reads first 2KB = valid for both
// int32[512] and int64[512]). int32 misread as int64 => OOB => int32.
// -------------------------------------------------------------------------
__device__ __forceinline__ int detect64(const void* sampled, int tid, int* sh) {
    if (tid == 0) *sh = 0;
    __syncthreads();
    const long long* s64 = (const long long*)sampled;
    for (int i = tid; i < 256; i += blockDim.x) {
        long long v = s64[i];
        if (v < 0 || v >= VOC_) *sh = 1;
    }
    __syncthreads();
    return *sh ? 0 : 1;
}
__device__ __forceinline__ int load_id(const void* p, int i, int idx64) {
    long long v;
    if (idx64) v = ((const long long*)p)[i];
    else       v = (long long)((const int*)p)[i];
    if (v < 0) v = 0;
    if (v >= VOC_) v = VOC_ - 1;
    return (int)v;
}

// -------------------------------------------------------------------------
// Reference-faithful  -log(expected_count(id))  (cancellation-safe)
// -------------------------------------------------------------------------
__device__ __forceinline__ float neg_log_expected(int id) {
    double cd = (double)id;
    float l2 = (float)log(cd + 2.0);
    float l1 = (float)log(cd + 1.0);
    float denom = (float)log((double)VOC_ + 1.0);
    float p = (l2 - l1) / denom;
    float lp = log1pf(-p);
    float e  = -expm1f(512.0f * lp);
    return -logf(e);
}

// -------------------------------------------------------------------------
// MUFU softplus: max(x,0) + ln2*lg2(1 + ex2(-|x|*log2e)). 6 instr, 2 MUFU.
// abs err ~1e-6 per element (budget ~3e-4) — offloads the epilogue from
// the issue/FMA pipes to the idle MUFU pipe.
// -------------------------------------------------------------------------
__device__ __forceinline__ float softplus_mufu(float x) {
    float mx = fmaxf(x, 0.0f);
    float y  = fabsf(x) * -1.4426950408889634f;
    float t, l;
    asm("ex2.approx.ftz.f32 %0, %1;" : "=f"(t) : "f"(y));
    asm("lg2.approx.ftz.f32 %0, %1;" : "=f"(l) : "f"(1.0f + t));
    return fmaf(0.69314718055994531f, l, mx);
}

__device__ __forceinline__ uint32_t pack_bf(float a, float b) {
    __nv_bfloat162 h = __floats2bfloat162_rn(a, b);
    return *reinterpret_cast<uint32_t*>(&h);
}

// -------------------------------------------------------------------------
// K_prep (256 thr): bx [0,32)  gather B rows -> swizzled bf16 + sampled corr
//                   bx [32,96) per-label corr (fp64 logs, fully parallel)
// -------------------------------------------------------------------------
__global__ void k_prep(const float* __restrict__ W, const float* __restrict__ bias,
                       const void* __restrict__ sampled,
                       const void* __restrict__ labels) {
    __shared__ int shf;
    int bx = blockIdx.x, t = threadIdx.x;
    int idx64 = detect64(sampled, t, &shf);
    if (bx == 0 && t == 0) g_idx64 = idx64;
    if (bx < 32) {
        int sl = t >> 4;                 // 0..15 sample within block
        int kg = t & 15;                 // 16B k-chunk
        int s  = bx * 16 + sl;
        int id = load_id(sampled, s, idx64);
        const float* src = W + (size_t)id * E_ + kg * 8;
        float4 v0 = *(const float4*)src;
        float4 v1 = *(const float4*)(src + 4);
        uint4 u;
        u.x = pack_bf(v0.x, v0.y); u.y = pack_bf(v0.z, v0.w);
        u.z = pack_bf(v1.x, v1.y); u.w = pack_bf(v1.z, v1.w);
        int colTile = s >> 7, n = s & 127;
        *(uint4*)((char*)g_Bsw + colTile * TILE_BYTES + tile_off(n, kg)) = u;
        if (kg == 0)
            g_corr[s] = bias[id] + neg_log_expected(id);
    } else {
        int i = (bx - 32) * 256 + t;
        int id = load_id(labels, i, idx64);
        g_tcorr[i] = bias[id] + neg_log_expected(id);
    }
}

#define LDMX4(r0, r1, r2, r3, addr) \
    asm volatile("ldmatrix.sync.aligned.m8n8.x4.shared.b16 {%0,%1,%2,%3}, [%4];" \
                 : "=r"(r0), "=r"(r1), "=r"(r2), "=r"(r3) : "r"(addr))

#define MMA16816(c, a, b0, b1) \
    asm volatile("mma.sync.aligned.m16n8k16.row.col.f32.bf16.bf16.f32 " \
                 "{%0,%1,%2,%3}, {%4,%5,%6,%7}, {%8,%9}, {%0,%1,%2,%3};" \
                 : "+f"((c)[0]), "+f"((c)[1]), "+f"((c)[2]), "+f"((c)[3]) \
                 : "r"((a)[0]), "r"((a)[1]), "r"((a)[2]), "r"((a)[3]), \
                   "r"(b0), "r"(b1))

// -------------------------------------------------------------------------
// K_main: blocks [0,512)   bf16 HMMA 128x128 GEMM tile + softplus + partial
//         blocks [512,768) true-class loss, 64 rows each (concurrent)
//         last block:      deterministic double final reduction
// block = 256 threads (8 warps, 4x2), warp tile 32x64, dyn smem = 64KB
// -------------------------------------------------------------------------
__global__ __launch_bounds__(256, 2)
void k_main(const float* __restrict__ P, const float* __restrict__ W,
            const void* __restrict__ labels, float* __restrict__ out) {
    __shared__ float red[8];
    __shared__ double dred[256];
    __shared__ unsigned int ticket;
    extern __shared__ char dyn[];

    const int bx = blockIdx.x;
    const int tid = threadIdx.x, lane = tid & 31, wid = tid >> 5;
    float partial = 0.0f;

    if (bx < NGEMM) {
        const int rowTile = bx >> 2, colTile = bx & 3;
        char* Abuf = dyn;
        char* Bbuf = dyn + TILE_BYTES;

        // Stage A (f32 -> bf16, swizzled) and B (16B copies, pre-swizzled)
        const float* Abase = P + (size_t)rowTile * 128 * E_;
#pragma unroll
        for (int i = 0; i < 8; i++) {
            int idx = tid + 256 * i;               // 0..2047
            int r = idx >> 4, c = idx & 15;
            const float* src = Abase + (size_t)r * E_ + c * 8;
            float4 v0 = *(const float4*)src;
            float4 v1 = *(const float4*)(src + 4);
            uint4 u;
            u.x = pack_bf(v0.x, v0.y); u.y = pack_bf(v0.z, v0.w);
            u.z = pack_bf(v1.x, v1.y); u.w = pack_bf(v1.z, v1.w);
            *(uint4*)(Abuf + tile_off(r, c)) = u;
        }
        const uint4* Bsrc = (const uint4*)((const char*)g_Bsw + colTile * TILE_BYTES);
#pragma unroll
        for (int i = 0; i < 8; i++)
            ((uint4*)Bbuf)[tid + 256 * i] = Bsrc[tid + 256 * i];
        __syncthreads();

        const int warpRow = wid & 3;          // m offset *32
        const int warpCol = wid >> 2;         // n offset *64
        const int lrow = lane & 15;
        const int lhi  = lane >> 4;

        const uint32_t a_s = smem_u32(Abuf);
        const uint32_t b_s = smem_u32(Bbuf);

        int arow[2], brow[4];
#pragma unroll
        for (int mi = 0; mi < 2; mi++) arow[mi] = warpRow * 32 + mi * 16 + lrow;
#pragma unroll
        for (int nj = 0; nj < 4; nj++) brow[nj] = warpCol * 64 + nj * 16 + lrow;

        float acc[2][8][4];
#pragma unroll
        for (int mi = 0; mi < 2; mi++)
#pragma unroll
            for (int ni = 0; ni < 8; ni++)
#pragma unroll
                for (int r = 0; r < 4; r++) acc[mi][ni][r] = 0.0f;

#pragma unroll
        for (int ks = 0; ks < 8; ks++) {
            const int chunk = ks * 2 + lhi;
            uint32_t a[2][4];
#pragma unroll
            for (int mi = 0; mi < 2; mi++) {
                uint32_t addr = a_s + (uint32_t)(arow[mi] * 256
                               + ((chunk ^ (arow[mi] & 7)) << 4));
                LDMX4(a[mi][0], a[mi][1], a[mi][2], a[mi][3], addr);
            }
            uint32_t bb[4][4];
#pragma unroll
            for (int nj = 0; nj < 4; nj++) {
                uint32_t addr = b_s + (uint32_t)(brow[nj] * 256
                               + ((chunk ^ (brow[nj] & 7)) << 4));
                LDMX4(bb[nj][0], bb[nj][1], bb[nj][2], bb[nj][3], addr);
            }
#pragma unroll
            for (int mi = 0; mi < 2; mi++)
#pragma unroll
                for (int ni = 0; ni < 8; ni++)
                    MMA16816(acc[mi][ni], a[mi],
                             bb[ni >> 1][ni & 1], bb[ni >> 1][2 + (ni & 1)]);
        }

        // Epilogue: cols colTile*128 + warpCol*64 + ni*8 + q*2 (+1)
        const int q = lane & 3;
        const float* corrB = g_corr + colTile * 128 + warpCol * 64;
        float lsum = 0.0f;
#pragma unroll
        for (int ni = 0; ni < 8; ni++) {
            float c0 = corrB[ni * 8 + q * 2];
            float c1 = corrB[ni * 8 + q * 2 + 1];
#pragma unroll
            for (int mi = 0; mi < 2; mi++) {
                lsum += softplus_mufu(acc[mi][ni][0] + c0);
                lsum += softplus_mufu(acc[mi][ni][1] + c1);
                lsum += softplus_mufu(acc[mi][ni][2] + c0);
                lsum += softplus_mufu(acc[mi][ni][3] + c1);
            }
        }
        partial = lsum;
    } else {
        // True-class loss: 64 rows per block, 8 rows per warp, prefetched.
        const int idx64 = g_idx64;
        const int rowbase = (bx - NGEMM) * 64 + wid * 8;

        int cid = 0;
        if (lane < 8) cid = load_id(labels, rowbase + lane, idx64);

        float wsum = 0.0f;
        int id0 = __shfl_sync(0xFFFFFFFFu, cid, 0);
        float4 p4 = *(const float4*)(P + (size_t)rowbase * E_ + lane * 4);
        float4 w4 = *(const float4*)(W + (size_t)id0 * E_ + lane * 4);
#pragma unroll
        for (int i = 0; i < 8; i++) {
            float4 np, nw;
            if (i < 7) {
                int idn = __shfl_sync(0xFFFFFFFFu, cid, i + 1);
                np = *(const float4*)(P + (size_t)(rowbase + i + 1) * E_ + lane * 4);
                nw = *(const float4*)(W + (size_t)idn * E_ + lane * 4);
            } else {
                np = make_float4(0.f, 0.f, 0.f, 0.f);
                nw = np;
            }
            float d = p4.x * w4.x + p4.y * w4.y + p4.z * w4.z + p4.w * w4.w;
#pragma unroll
            for (int off = 16; off > 0; off >>= 1)
                d += __shfl_xor_sync(0xFFFFFFFFu, d, off);
            if (lane == 0) {
                float x = d + g_tcorr[rowbase + i];
                wsum += softplus_mufu(x) - x;   // sce(x, z=1)
            }
            p4 = np; w4 = nw;
        }
        partial = (lane == 0) ? wsum : 0.0f;
    }

    // Block reduction: warp shuffle + one cross-warp stage.
#pragma unroll
    for (int off = 16; off > 0; off >>= 1)
        partial += __shfl_xor_sync(0xFFFFFFFFu, partial, off);
    if (lane == 0) red[wid] = partial;
    __syncthreads();
    if (tid == 0) {
        float t = 0.0f;
#pragma unroll
        for (int i = 0; i < 8; i++) t += red[i];
        g_part[bx] = t;
    }

    // Last-block deterministic final reduction.
    __threadfence();
    if (tid == 0) ticket = atomicAdd(&g_done, 1u);
    __syncthreads();
    if (ticket == NTOT - 1) {
        __threadfence();
        double s = 0.0;
        for (int i = tid; i < NTOT; i += 256) s += (double)g_part[i];
        dred[tid] = s;
        __syncthreads();
#pragma unroll
        for (int k = 128; k > 0; k >>= 1) {
            if (tid < k) dred[tid] += dred[tid + k];
            __syncthreads();
        }
        if (tid == 0) {
            out[0] = (float)(dred[0] / (double)B_);
            g_done = 0;                  // reset for next graph replay
        }
    }
}

// -------------------------------------------------------------------------
extern "C" void kernel_launch(void* const* d_in, const int* in_sizes, int n_in,
                              void* d_out, int out_size) {
    const float* pred    = (const float*)d_in[0];   // [B, E]
    const float* weights = (const float*)d_in[1];   // [V, E]
    const float* biases  = (const float*)d_in[2];   // [V]
    const void*  labels  = d_in[3];                 // [B, 1] int32 or int64
    const void*  sampled = d_in[4];                 // [S]
    float* out = (float*)d_out;

    static int attr_done = 0;
    if (!attr_done) {
        cudaFuncSetAttribute(k_main, cudaFuncAttributeMaxDynamicSharedMemorySize,
                             DYN_SMEM);
        attr_done = 1;
    }

    k_prep<<<96, 256>>>(weights, biases, sampled, labels);
    k_main<<<NTOT, 256, DYN_SMEM>>>(pred, weights, labels, out);
}

// round 14
// speedup vs baseline: 2.0649x; 1.1486x over previous
#include <cuda_runtime.h>
#include <cuda_bf16.h>
#include <math.h>
#include <stdint.h>

// Problem constants (fixed by the dataset)
#define B_   16384
#define E_   128
#define S_   512
#define VOC_ 1000000

#define NGEMM 512                     // 128 row-tiles x 4 col-tiles
#define NTRUE 256                     // 64 true rows each
#define NTOT  (NGEMM + NTRUE)

#define TILE_BYTES 32768              // 128 rows x 128 bf16 (256B/row)
#define DYN_SMEM (2 * TILE_BYTES)

// ---- device scratch (no allocations allowed) ----
__device__ uint32_t g_Bsw[4 * TILE_BYTES / 4];   // pre-swizzled bf16 B tiles
__device__ float g_corr[S_];
__device__ float g_part[NTOT];
__device__ int   g_idx64;
__device__ unsigned int g_done;       // zero-init; last block resets each run

__device__ __forceinline__ uint32_t smem_u32(const void* p) {
    uint32_t a;
    asm("{ .reg .u64 t; cvta.to.shared.u64 t, %1; cvt.u32.u64 %0, t; }"
        : "=r"(a) : "l"(p));
    return a;
}

// Swizzled tile layout: [row r][16B chunk c], phys chunk = c ^ (r&7).
__device__ __forceinline__ uint32_t tile_off(int r, int c) {
    return (uint32_t)(r * 256 + ((c ^ (r & 7)) << 4));
}

// -------------------------------------------------------------------------
// Index dtype detection (per-block, reads first 2KB = valid for both
// int32[512] and int64[512]). int32 misread as int64 => OOB => int32.
// -------------------------------------------------------------------------
__device__ __forceinline__ int detect64(const void* sampled, int tid, int* sh) {
    if (tid == 0) *sh = 0;
    __syncthreads();
    const long long* s64 = (const long long*)sampled;
    for (int i = tid; i < 256; i += blockDim.x) {
        long long v = s64[i];
        if (v < 0 || v >= VOC_) *sh = 1;
    }
    __syncthreads();
    return *sh ? 0 : 1;
}
__device__ __forceinline__ int load_id(const void* p, int i, int idx64) {
    long long v;
    if (idx64) v = ((const long long*)p)[i];
    else       v = (long long)((const int*)p)[i];
    if (v < 0) v = 0;
    if (v >= VOC_) v = VOC_ - 1;
    return (int)v;
}

// -------------------------------------------------------------------------
// Reference-faithful  -log(expected_count(id)), fp64-CR path. Used ONLY for
// the 512 sampled ids (full sensitivity ~1 each in the mean loss).
// -------------------------------------------------------------------------
__device__ __forceinline__ float neg_log_expected(int id) {
    double cd = (double)id;
    float l2 = (float)log(cd + 2.0);
    float l1 = (float)log(cd + 1.0);
    float denom = (float)log((double)VOC_ + 1.0);
    float p = (l2 - l1) / denom;
    float lp = log1pf(-p);
    float e  = -expm1f(512.0f * lp);
    return -logf(e);
}

// -------------------------------------------------------------------------
// Fast f32 path for LABEL corrections. Sensitivity of the true-class loss
// to corr is |sigmoid(x)-1| ~ e^-9 for large-c ids (the only regime where
// f32 log cancellation is inaccurate); small-c ids (real sensitivity) have
// no cancellation. Clamp e to avoid inf when the f32 diff rounds to 0.
// -------------------------------------------------------------------------
__device__ __forceinline__ float neg_log_expected_f32(int id) {
    float c  = (float)id;
    float l2 = logf(c + 2.0f);
    float l1 = logf(c + 1.0f);
    float p  = (l2 - l1) * (1.0f / 13.815512f);   // 1/float(log(VOC+1))
    float lp = log1pf(-fminf(p, 0.9999999f));
    float e  = -expm1f(512.0f * lp);
    e = fmaxf(e, 1e-37f);
    return -logf(e);
}

// -------------------------------------------------------------------------
// MUFU softplus: max(x,0) + ln2*lg2(1 + ex2(-|x|*log2e)). 2 MUFU, 4 FMA.
// -------------------------------------------------------------------------
__device__ __forceinline__ float softplus_mufu(float x) {
    float mx = fmaxf(x, 0.0f);
    float y  = fabsf(x) * -1.4426950408889634f;
    float t, l;
    asm("ex2.approx.ftz.f32 %0, %1;" : "=f"(t) : "f"(y));
    asm("lg2.approx.ftz.f32 %0, %1;" : "=f"(l) : "f"(1.0f + t));
    return fmaf(0.69314718055994531f, l, mx);
}

__device__ __forceinline__ uint32_t pack_bf(float a, float b) {
    __nv_bfloat162 h = __floats2bfloat162_rn(a, b);
    return *reinterpret_cast<uint32_t*>(&h);
}

// -------------------------------------------------------------------------
// K_prep (32 blocks x 256 thr): gather sampled weight rows -> swizzled bf16
// tiles; threads 0..15 also compute the 16 sampled corrs (fp64, hidden
// behind the gather latency).
// -------------------------------------------------------------------------
__global__ void k_prep(const float* __restrict__ W, const float* __restrict__ bias,
                       const void* __restrict__ sampled) {
    __shared__ int shf;
    int bx = blockIdx.x, t = threadIdx.x;
    int idx64 = detect64(sampled, t, &shf);
    if (bx == 0 && t == 0) g_idx64 = idx64;

    if (t < 16) {
        int s = bx * 16 + t;
        int id = load_id(sampled, s, idx64);
        g_corr[s] = bias[id] + neg_log_expected(id);
    }

    int sl = t >> 4;                 // 0..15 sample within block
    int kg = t & 15;                 // 16B k-chunk
    int s  = bx * 16 + sl;
    int id = load_id(sampled, s, idx64);
    const float* src = W + (size_t)id * E_ + kg * 8;
    float4 v0 = *(const float4*)src;
    float4 v1 = *(const float4*)(src + 4);
    uint4 u;
    u.x = pack_bf(v0.x, v0.y); u.y = pack_bf(v0.z, v0.w);
    u.z = pack_bf(v1.x, v1.y); u.w = pack_bf(v1.z, v1.w);
    int colTile = s >> 7, n = s & 127;
    *(uint4*)((char*)g_Bsw + colTile * TILE_BYTES + tile_off(n, kg)) = u;
}

#define LDMX4(r0, r1, r2, r3, addr) \
    asm volatile("ldmatrix.sync.aligned.m8n8.x4.shared.b16 {%0,%1,%2,%3}, [%4];" \
                 : "=r"(r0), "=r"(r1), "=r"(r2), "=r"(r3) : "r"(addr))

#define MMA16816(c, a, b0, b1) \
    asm volatile("mma.sync.aligned.m16n8k16.row.col.f32.bf16.bf16.f32 " \
                 "{%0,%1,%2,%3}, {%4,%5,%6,%7}, {%8,%9}, {%0,%1,%2,%3};" \
                 : "+f"((c)[0]), "+f"((c)[1]), "+f"((c)[2]), "+f"((c)[3]) \
                 : "r"((a)[0]), "r"((a)[1]), "r"((a)[2]), "r"((a)[3]), \
                   "r"(b0), "r"(b1))

// -------------------------------------------------------------------------
// K_main: blocks [0,512)   bf16 HMMA 128x128 GEMM tile + softplus + partial
//         blocks [512,768) true-class loss, 64 rows each (corr in-lane f32)
//         last block:      deterministic double final reduction
// block = 256 threads (8 warps, 4x2), warp tile 32x64, dyn smem = 64KB
// -------------------------------------------------------------------------
__global__ __launch_bounds__(256, 2)
void k_main(const float* __restrict__ P, const float* __restrict__ W,
            const float* __restrict__ bias, const void* __restrict__ labels,
            float* __restrict__ out) {
    __shared__ float red[8];
    __shared__ double dred[256];
    __shared__ unsigned int ticket;
    extern __shared__ char dyn[];

    const int bx = blockIdx.x;
    const int tid = threadIdx.x, lane = tid & 31, wid = tid >> 5;
    float partial = 0.0f;

    if (bx < NGEMM) {
        const int rowTile = bx >> 2, colTile = bx & 3;
        char* Abuf = dyn;
        char* Bbuf = dyn + TILE_BYTES;

        // Stage A (f32 -> bf16, swizzled) and B (16B copies, pre-swizzled)
        const float* Abase = P + (size_t)rowTile * 128 * E_;
#pragma unroll
        for (int i = 0; i < 8; i++) {
            int idx = tid + 256 * i;               // 0..2047
            int r = idx >> 4, c = idx & 15;
            const float* src = Abase + (size_t)r * E_ + c * 8;
            float4 v0 = *(const float4*)src;
            float4 v1 = *(const float4*)(src + 4);
            uint4 u;
            u.x = pack_bf(v0.x, v0.y); u.y = pack_bf(v0.z, v0.w);
            u.z = pack_bf(v1.x, v1.y); u.w = pack_bf(v1.z, v1.w);
            *(uint4*)(Abuf + tile_off(r, c)) = u;
        }
        const uint4* Bsrc = (const uint4*)((const char*)g_Bsw + colTile * TILE_BYTES);
#pragma unroll
        for (int i = 0; i < 8; i++)
            ((uint4*)Bbuf)[tid + 256 * i] = Bsrc[tid + 256 * i];
        __syncthreads();

        const int warpRow = wid & 3;          // m offset *32
        const int warpCol = wid >> 2;         // n offset *64
        const int lrow = lane & 15;
        const int lhi  = lane >> 4;

        const uint32_t a_s = smem_u32(Abuf);
        const uint32_t b_s = smem_u32(Bbuf);

        int arow[2], brow[4];
#pragma unroll
        for (int mi = 0; mi < 2; mi++) arow[mi] = warpRow * 32 + mi * 16 + lrow;
#pragma unroll
        for (int nj = 0; nj < 4; nj++) brow[nj] = warpCol * 64 + nj * 16 + lrow;

        float acc[2][8][4];
#pragma unroll
        for (int mi = 0; mi < 2; mi++)
#pragma unroll
            for (int ni = 0; ni < 8; ni++)
#pragma unroll
                for (int r = 0; r < 4; r++) acc[mi][ni][r] = 0.0f;

#pragma unroll
        for (int ks = 0; ks < 8; ks++) {
            const int chunk = ks * 2 + lhi;
            uint32_t a[2][4];
#pragma unroll
            for (int mi = 0; mi < 2; mi++) {
                uint32_t addr = a_s + (uint32_t)(arow[mi] * 256
                               + ((chunk ^ (arow[mi] & 7)) << 4));
                LDMX4(a[mi][0], a[mi][1], a[mi][2], a[mi][3], addr);
            }
            uint32_t bb[4][4];
#pragma unroll
            for (int nj = 0; nj < 4; nj++) {
                uint32_t addr = b_s + (uint32_t)(brow[nj] * 256
                               + ((chunk ^ (brow[nj] & 7)) << 4));
                LDMX4(bb[nj][0], bb[nj][1], bb[nj][2], bb[nj][3], addr);
            }
#pragma unroll
            for (int mi = 0; mi < 2; mi++)
#pragma unroll
                for (int ni = 0; ni < 8; ni++)
                    MMA16816(acc[mi][ni], a[mi],
                             bb[ni >> 1][ni & 1], bb[ni >> 1][2 + (ni & 1)]);
        }

        // Epilogue: cols colTile*128 + warpCol*64 + ni*8 + q*2 (+1)
        const int q = lane & 3;
        const float* corrB = g_corr + colTile * 128 + warpCol * 64;
        float lsum = 0.0f;
#pragma unroll
        for (int ni = 0; ni < 8; ni++) {
            float c0 = corrB[ni * 8 + q * 2];
            float c1 = corrB[ni * 8 + q * 2 + 1];
#pragma unroll
            for (int mi = 0; mi < 2; mi++) {
                lsum += softplus_mufu(acc[mi][ni][0] + c0);
                lsum += softplus_mufu(acc[mi][ni][1] + c1);
                lsum += softplus_mufu(acc[mi][ni][2] + c0);
                lsum += softplus_mufu(acc[mi][ni][3] + c1);
            }
        }
        partial = lsum;
    } else {
        // True-class loss: 64 rows per block, 8 rows per warp.
        const int idx64 = g_idx64;
        const int rowbase = (bx - NGEMM) * 64 + wid * 8;

        // Lanes 0..7: label id + f32 correction for one row each (cheap,
        // overlaps the gathers below).
        int cid = 0;
        float mycorr = 0.0f;
        if (lane < 8) {
            cid = load_id(labels, rowbase + lane, idx64);
            mycorr = bias[cid] + neg_log_expected_f32(cid);
        }

        float wsum = 0.0f;
        int id0 = __shfl_sync(0xFFFFFFFFu, cid, 0);
        float4 p4 = *(const float4*)(P + (size_t)rowbase * E_ + lane * 4);
        float4 w4 = *(const float4*)(W + (size_t)id0 * E_ + lane * 4);
#pragma unroll
        for (int i = 0; i < 8; i++) {
            float4 np, nw;
            if (i < 7) {
                int idn = __shfl_sync(0xFFFFFFFFu, cid, i + 1);
                np = *(const float4*)(P + (size_t)(rowbase + i + 1) * E_ + lane * 4);
                nw = *(const float4*)(W + (size_t)idn * E_ + lane * 4);
            } else {
                np = make_float4(0.f, 0.f, 0.f, 0.f);
                nw = np;
            }
            float d = p4.x * w4.x + p4.y * w4.y + p4.z * w4.z + p4.w * w4.w;
#pragma unroll
            for (int off = 16; off > 0; off >>= 1)
                d += __shfl_xor_sync(0xFFFFFFFFu, d, off);
            float ci = __shfl_sync(0xFFFFFFFFu, mycorr, i);
            if (lane == 0) {
                float x = d + ci;
                wsum += softplus_mufu(x) - x;   // sce(x, z=1)
            }
            p4 = np; w4 = nw;
        }
        partial = (lane == 0) ? wsum : 0.0f;
    }

    // Block reduction: warp shuffle + one cross-warp stage.
#pragma unroll
    for (int off = 16; off > 0; off >>= 1)
        partial += __shfl_xor_sync(0xFFFFFFFFu, partial, off);
    if (lane == 0) red[wid] = partial;
    __syncthreads();
    if (tid == 0) {
        float t = 0.0f;
#pragma unroll
        for (int i = 0; i < 8; i++) t += red[i];
        g_part[bx] = t;
    }

    // Last-block deterministic final reduction.
    __threadfence();
    if (tid == 0) ticket = atomicAdd(&g_done, 1u);
    __syncthreads();
    if (ticket == NTOT - 1) {
        __threadfence();
        double s = 0.0;
        for (int i = tid; i < NTOT; i += 256) s += (double)g_part[i];
        dred[tid] = s;
        __syncthreads();
#pragma unroll
        for (int k = 128; k > 0; k >>= 1) {
            if (tid < k) dred[tid] += dred[tid + k];
            __syncthreads();
        }
        if (tid == 0) {
            out[0] = (float)(dred[0] / (double)B_);
            g_done = 0;                  // reset for next graph replay
        }
    }
}

// -------------------------------------------------------------------------
extern "C" void kernel_launch(void* const* d_in, const int* in_sizes, int n_in,
                              void* d_out, int out_size) {
    const float* pred    = (const float*)d_in[0];   // [B, E]
    const float* weights = (const float*)d_in[1];   // [V, E]
    const float* biases  = (const float*)d_in[2];   // [V]
    const void*  labels  = d_in[3];                 // [B, 1] int32 or int64
    const void*  sampled = d_in[4];                 // [S]
    float* out = (float*)d_out;

    static int attr_done = 0;
    if (!attr_done) {
        cudaFuncSetAttribute(k_main, cudaFuncAttributeMaxDynamicSharedMemorySize,
                             DYN_SMEM);
        attr_done = 1;
    }

    k_prep<<<32, 256>>>(weights, biases, sampled);
    k_main<<<NTOT, 256, DYN_SMEM>>>(pred, weights, biases, labels, out);
}